// round 16
// baseline (speedup 1.0000x reference)
#include <cuda_runtime.h>
#include <cuda_fp16.h>
#include <math.h>
#include <stdint.h>

#define NN      60000
#define IN_C    128
#define HID     512
#define D_CAT   1024
#define D_FC    2048
#define D_L1    4096
#define OUT_C   64
#define BN_EPS  1e-5f

#define EPI_NONE    0
#define EPI_RELU    1
#define EPI_BNRELU  2
#define EPI_LEAKY   3
#define EPI_SIGMOID 4

typedef __half f16;

// ---------------------------------------------------------------------------
// Scratch (__device__ globals; no allocations allowed)
// ---------------------------------------------------------------------------
__device__ float g_h[(size_t)NN * IN_C];
__device__ f16  g_hf [(size_t)NN * IN_C ];
__device__ f16  g_t  [(size_t)NN * D_CAT];
__device__ f16  g_c  [(size_t)NN * D_CAT];
__device__ f16  g_fc [(size_t)NN * D_FC ];
// weights fp16 [N,K]
__device__ f16 g_w1ab[D_CAT * IN_C];
__device__ f16 g_w2a[HID * HID];
__device__ f16 g_w2b[HID * HID];
__device__ f16 g_wfc[D_FC * D_CAT];
__device__ f16 g_wl1[(size_t)D_FC * D_L1];
__device__ f16 g_wl2[(size_t)D_L1 * D_FC];
__device__ f16 g_wo [OUT_C * D_FC];
// fold intermediates / results
__device__ f16  g_w2c [OUT_C * D_L1];
__device__ f16  g_wall[OUT_C * D_FC];
__device__ float g_bias1[D_FC];
__device__ float g_ball [OUT_C];
__device__ float g_zerobias[D_L1];
// concatenated BN params
__device__ float g_bnb[D_CAT], g_bng[D_CAT], g_bnbt[D_CAT], g_bnm[D_CAT], g_bnv[D_CAT];

// ---------------------------------------------------------------------------
// helpers
// ---------------------------------------------------------------------------
__device__ __forceinline__ uint32_t smem_u32(const void* p) {
    uint32_t a;
    asm("{ .reg .u64 t; cvta.to.shared.u64 t, %1; cvt.u32.u64 %0, t; }" : "=r"(a) : "l"(p));
    return a;
}

#define LDSM4(r, a) \
    asm volatile("ldmatrix.sync.aligned.m8n8.x4.shared.b16 {%0,%1,%2,%3}, [%4];" \
        : "=r"((r)[0]), "=r"((r)[1]), "=r"((r)[2]), "=r"((r)[3]) : "r"(a))

#define MMA_F16(d, a, b) \
    asm volatile("mma.sync.aligned.m16n8k16.row.col.f32.f16.f16.f32 " \
        "{%0,%1,%2,%3}, {%4,%5,%6,%7}, {%8,%9}, {%0,%1,%2,%3};" \
        : "+f"((d)[0]), "+f"((d)[1]), "+f"((d)[2]), "+f"((d)[3]) \
        : "r"((a)[0]), "r"((a)[1]), "r"((a)[2]), "r"((a)[3]), "r"((b)[0]), "r"((b)[1]))

#define CP_ASYNC(dst, src, ok) \
    asm volatile("cp.async.cg.shared.global [%0], [%1], 16, %2;" \
        :: "r"(dst), "l"(src), "r"(ok) : "memory")
#define CP_COMMIT()  asm volatile("cp.async.commit_group;" ::: "memory")
#define CP_WAIT2()   asm volatile("cp.async.wait_group 2;" ::: "memory")

// ---------------------------------------------------------------------------
// small kernels
// ---------------------------------------------------------------------------
__global__ void copy_x_kernel(const float4* __restrict__ x, float4* __restrict__ h, int n4) {
    int i = blockIdx.x * blockDim.x + threadIdx.x;
    if (i < n4) h[i] = x[i];
}

__global__ void edge_agg_kernel(const float* __restrict__ x, const int* __restrict__ ei,
                                float* __restrict__ h, int n_edges) {
    int warp = (blockIdx.x * blockDim.x + threadIdx.x) >> 5;
    int lane = threadIdx.x & 31;
    if (warp >= n_edges) return;
    int src = ei[warp];
    int dst = ei[n_edges + warp];
    const float4 v = *reinterpret_cast<const float4*>(x + (size_t)src * IN_C + lane * 4);
    float* d = h + (size_t)dst * IN_C + lane * 4;
    asm volatile("red.global.add.v4.f32 [%0], {%1, %2, %3, %4};"
                 :: "l"(d), "f"(v.x), "f"(v.y), "f"(v.z), "f"(v.w) : "memory");
}

// fp32 -> fp16 convert, 4 / thread
__global__ void conv_kernel(const float4* __restrict__ in, uint2* __restrict__ o, int n4) {
    int i = blockIdx.x * blockDim.x + threadIdx.x;
    if (i >= n4) return;
    float4 v = in[i];
    __half2 h01 = __floats2half2_rn(v.x, v.y);
    __half2 h23 = __floats2half2_rn(v.z, v.w);
    uint2 u; u.x = *(uint32_t*)&h01; u.y = *(uint32_t*)&h23;
    o[i] = u;
}

// two fp32 -> fp16 converts in one launch
__global__ void conv2_kernel(const float4* __restrict__ a, const float4* __restrict__ b,
                             uint2* __restrict__ ao, uint2* __restrict__ bo, int n4) {
    int i = blockIdx.x * blockDim.x + threadIdx.x;
    const float4* src; uint2* dst; int idx;
    if (i < n4)          { src = a; dst = ao; idx = i; }
    else if (i < 2 * n4) { src = b; dst = bo; idx = i - n4; }
    else return;
    float4 v = src[idx];
    __half2 h01 = __floats2half2_rn(v.x, v.y);
    __half2 h23 = __floats2half2_rn(v.z, v.w);
    uint2 u; u.x = *(uint32_t*)&h01; u.y = *(uint32_t*)&h23;
    dst[idx] = u;
}

// paired transpose -> fp16: z selects (W, dst)
__global__ void wtrans2_kernel(const float* __restrict__ W0, const float* __restrict__ W1,
                               f16* o0, f16* o1, int K, int N) {
    const float* W = blockIdx.z ? W1 : W0;
    f16* o = blockIdx.z ? o1 : o0;
    __shared__ float t[32][33];
    int n0 = blockIdx.x * 32, k0 = blockIdx.y * 32;
#pragma unroll
    for (int dy = 0; dy < 32; dy += 8) {
        int k = k0 + threadIdx.y + dy, n = n0 + threadIdx.x;
        t[threadIdx.y + dy][threadIdx.x] = (k < K && n < N) ? W[(size_t)k * N + n] : 0.f;
    }
    __syncthreads();
#pragma unroll
    for (int dy = 0; dy < 32; dy += 8) {
        int n = n0 + threadIdx.y + dy, k = k0 + threadIdx.x;
        if (n < N && k < K)
            o[(size_t)n * K + k] = __float2half(t[threadIdx.x][threadIdx.y + dy]);
    }
}

__global__ void wtrans_kernel(const float* __restrict__ W, f16* __restrict__ o, int K, int N) {
    __shared__ float t[32][33];
    int n0 = blockIdx.x * 32, k0 = blockIdx.y * 32;
#pragma unroll
    for (int dy = 0; dy < 32; dy += 8) {
        int k = k0 + threadIdx.y + dy, n = n0 + threadIdx.x;
        t[threadIdx.y + dy][threadIdx.x] = (k < K && n < N) ? W[(size_t)k * N + n] : 0.f;
    }
    __syncthreads();
#pragma unroll
    for (int dy = 0; dy < 32; dy += 8) {
        int n = n0 + threadIdx.y + dy, k = k0 + threadIdx.x;
        if (n < N && k < K)
            o[(size_t)n * K + k] = __float2half(t[threadIdx.x][threadIdx.y + dy]);
    }
}

__global__ void concat_bn_kernel(const float* b1a, const float* b1b,
                                 const float* ga,  const float* gb,
                                 const float* bea, const float* beb,
                                 const float* ma,  const float* mb,
                                 const float* va,  const float* vb) {
    int i = threadIdx.x + blockIdx.x * blockDim.x;
    if (i >= HID) return;
    g_bnb [i] = b1a[i];  g_bnb [HID + i] = b1b[i];
    g_bng [i] = ga[i];   g_bng [HID + i] = gb[i];
    g_bnbt[i] = bea[i];  g_bnbt[HID + i] = beb[i];
    g_bnm [i] = ma[i];   g_bnm [HID + i] = mb[i];
    g_bnv [i] = va[i];   g_bnv [HID + i] = vb[i];
}

__global__ void bias_fold_kernel(const float* __restrict__ l1b,
                                 const float* __restrict__ l2w,
                                 const float* __restrict__ l2b,
                                 float* __restrict__ outb) {
    int n = blockIdx.x * blockDim.x + threadIdx.x;
    if (n >= D_FC) return;
    float s = l2b[n];
    for (int k = 0; k < D_L1; k++)
        s += l1b[k] * l2w[(size_t)k * D_FC + n];
    outb[n] = s;
}

__global__ void bias_fold2_kernel(const float* __restrict__ b1,
                                  const float* __restrict__ ow,
                                  const float* __restrict__ outb,
                                  float* __restrict__ ball) {
    int j = threadIdx.x;
    if (j >= OUT_C) return;
    float s = outb[j];
    for (int n = 0; n < D_FC; n++)
        s += b1[n] * ow[(size_t)n * OUT_C + j];
    ball[j] = s;
}

// ---------------------------------------------------------------------------
// fp16 mma.sync GEMM: C[M,N] = A[M,K](lda) @ B[N,K]^T, fp32 accumulate
// grid.z=2 dual mode: z=1 uses B2/bias2 and offsets A,C by zoffA/zoffC elements
// ---------------------------------------------------------------------------
#define STAGES 4

template <int BM_T, int BN_T, int TH>
__global__ __launch_bounds__(TH, 1)
void gemm_mma_kernel(const f16* __restrict__ A_gp, const f16* __restrict__ B_gp,
                     const f16* __restrict__ B2_gp, const float* __restrict__ bias2,
                     int zoffA, int zoffC,
                     f16* __restrict__ C16p, float* __restrict__ Cf,
                     const float* __restrict__ biasp,
                     const float* __restrict__ gamma, const float* __restrict__ beta,
                     const float* __restrict__ mean,  const float* __restrict__ var,
                     int M, int N, int K, int lda, int ldc, int epi)
{
    constexpr int A_BY   = BM_T * 64;
    constexpr int B_BY   = BN_T * 64;
    constexpr int OFF_B  = A_BY;
    constexpr int STG_B  = A_BY + B_BY;
    constexpr int WM     = TH / 64;
    constexpr int WTM    = BM_T / WM;
    constexpr int NI     = WTM / 16;
    constexpr int NJ     = BN_T / 16;
    constexpr int NJJ    = BN_T / 32;
    constexpr int A_IDS  = BM_T * 4;
    constexpr int PER    = (BM_T * 4 + BN_T * 4) / TH;

    const f16* A_g  = A_gp;
    const f16* B_g  = B_gp;
    f16* C16        = C16p;
    const float* bias = biasp;
    if (blockIdx.z) {
        A_g = A_gp + zoffA;
        C16 = C16p + zoffC;
        B_g = B2_gp;
        bias = bias2;
    }

    extern __shared__ __align__(128) char smem[];
    const uint32_t sb = smem_u32(smem);
    const int tid = threadIdx.x;
    const int lid = tid & 31, wid = tid >> 5;
    const int warpM = wid >> 1, warpN = wid & 1;
    const int m0 = blockIdx.y * BM_T, n0 = blockIdx.x * BN_T;
    const int NC = K >> 5;

    float acc[NI][NJ][4];
#pragma unroll
    for (int i = 0; i < NI; i++)
#pragma unroll
        for (int j = 0; j < NJ; j++)
#pragma unroll
            for (int q = 0; q < 4; q++) acc[i][j][q] = 0.0f;

    auto issue_stage = [&](int c, int s) {
        const int k0 = c << 5;
        const uint32_t stb = sb + s * STG_B;
#pragma unroll
        for (int q = 0; q < PER; q++) {
            int id = q * TH + tid;
            const f16* base;
            uint32_t toff;
            int row, ch, gr, rmax, ld;
            if (id < A_IDS) {
                row = id >> 2; ch = id & 3;
                base = A_g; toff = 0u;
                gr = m0 + row; rmax = M; ld = lda;
            } else {
                int idx = id - A_IDS;
                row = idx >> 2; ch = idx & 3;
                base = B_g; toff = (uint32_t)OFF_B;
                gr = n0 + row; rmax = N; ld = K;
            }
            unsigned ok = (gr < rmax) ? 16u : 0u;
            int rc = (gr < rmax) ? gr : 0;
            const char* src = (const char*)(base + (size_t)rc * ld + k0) + ch * 16;
            uint32_t dst = stb + toff + row * 64 + ((ch ^ ((row >> 1) & 3)) << 4);
            CP_ASYNC(dst, src, ok);
        }
        CP_COMMIT();
    };

    issue_stage(0, 0);
    issue_stage(1, 1);
    issue_stage(2, 2);

    const int grp = lid >> 3, lr = lid & 7;

    int s = 0;
    for (int c = 0; c < NC; c++) {
        CP_WAIT2();
        __syncthreads();
        if (c + 3 < NC) issue_stage(c + 3, (s + 3) & 3);
        else CP_COMMIT();

        const uint32_t stb = sb + s * STG_B;
#pragma unroll
        for (int ks = 0; ks < 2; ks++) {
            uint32_t a[NI][4];
#pragma unroll
            for (int i = 0; i < NI; i++) {
                int row = warpM * WTM + i * 16 + lr + ((grp & 1) << 3);
                int chk = 2 * ks + (grp >> 1);
                uint32_t ad = stb + row * 64 + ((chk ^ ((row >> 1) & 3)) << 4);
                LDSM4(a[i], ad);
            }
            uint32_t b[NJ][2];
#pragma unroll
            for (int jj = 0; jj < NJJ; jj++) {
                int row = warpN * (BN_T / 2) + jj * 16 + lr + ((grp >= 2) ? 8 : 0);
                int chk = 2 * ks + (grp & 1);
                uint32_t bd = stb + OFF_B + row * 64 + ((chk ^ ((row >> 1) & 3)) << 4);
                uint32_t r[4];
                LDSM4(r, bd);
                b[2 * jj][0] = r[0]; b[2 * jj][1] = r[1];
                b[2 * jj + 1][0] = r[2]; b[2 * jj + 1][1] = r[3];
            }
#pragma unroll
            for (int i = 0; i < NI; i++)
#pragma unroll
                for (int j = 0; j < NJ; j++)
                    MMA_F16(acc[i][j], a[i], b[j]);
        }
        s = (s + 1) & 3;
    }

    // ---- epilogue ----
    const int r_base = m0 + warpM * WTM + (lid >> 2);
    const int c_base = n0 + warpN * (BN_T / 2) + (lid & 3) * 2;
#pragma unroll
    for (int i = 0; i < NI; i++) {
#pragma unroll
        for (int half_r = 0; half_r < 2; half_r++) {
            int row = r_base + i * 16 + half_r * 8;
            if (row >= M) continue;
#pragma unroll
            for (int j = 0; j < NJ; j++) {
                int col = c_base + j * 8;
                if (col >= N) continue;
                float v0 = acc[i][j][half_r * 2 + 0] + bias[col];
                float v1 = acc[i][j][half_r * 2 + 1] + bias[col + 1];
                if (epi == EPI_BNRELU) {
                    v0 = (v0 - mean[col])     * rsqrtf(var[col] + BN_EPS)     * gamma[col]     + beta[col];
                    v1 = (v1 - mean[col + 1]) * rsqrtf(var[col + 1] + BN_EPS) * gamma[col + 1] + beta[col + 1];
                    v0 = fmaxf(v0, 0.0f); v1 = fmaxf(v1, 0.0f);
                } else if (epi == EPI_RELU) {
                    v0 = fmaxf(v0, 0.0f); v1 = fmaxf(v1, 0.0f);
                } else if (epi == EPI_LEAKY) {
                    v0 = (v0 > 0.0f) ? v0 : 0.01f * v0;
                    v1 = (v1 > 0.0f) ? v1 : 0.01f * v1;
                }
                if (epi == EPI_SIGMOID) {
                    float2 o;
                    o.x = 1.0f / (1.0f + expf(-v0));
                    o.y = 1.0f / (1.0f + expf(-v1));
                    *(float2*)(Cf + (size_t)row * ldc + col) = o;
                } else {
                    *(__half2*)(C16 + (size_t)row * ldc + col) = __floats2half2_rn(v0, v1);
                }
            }
        }
    }
}

// ---------------------------------------------------------------------------
// launch helpers
// ---------------------------------------------------------------------------
template <int BM_T, int BN_T, int TH>
static void launch_gemm(cudaStream_t st,
                        const f16* A, const f16* B,
                        f16* C16, float* Cf, const float* bias,
                        const float* ga, const float* be, const float* me, const float* va,
                        int M, int N, int K, int lda, int ldc, int epi) {
    dim3 grid((N + BN_T - 1) / BN_T, (M + BM_T - 1) / BM_T, 1);
    int smem = STAGES * (BM_T * 64 + BN_T * 64);
    gemm_mma_kernel<BM_T, BN_T, TH><<<grid, TH, smem, st>>>(
        A, B, B, bias, 0, 0, C16, Cf, bias, ga, be, me, va, M, N, K, lda, ldc, epi);
}

template <int BM_T, int BN_T, int TH>
static void launch_gemm_dual(cudaStream_t st,
                             const f16* A, const f16* B0, const f16* B1,
                             f16* C16, const float* bias0, const float* bias1,
                             int zoffA, int zoffC,
                             int M, int N, int K, int lda, int ldc, int epi) {
    dim3 grid((N + BN_T - 1) / BN_T, (M + BM_T - 1) / BM_T, 2);
    int smem = STAGES * (BM_T * 64 + BN_T * 64);
    gemm_mma_kernel<BM_T, BN_T, TH><<<grid, TH, smem, st>>>(
        A, B0, B1, bias1, zoffA, zoffC, C16, 0, bias0, 0, 0, 0, 0, M, N, K, lda, ldc, epi);
}

template <typename T> static T* sym(T* symbol) {
    void* p = nullptr;
    cudaGetSymbolAddress(&p, (const void*)symbol);
    return (T*)p;
}

extern "C" void kernel_launch(void* const* d_in, const int* in_sizes, int n_in,
                              void* d_out, int out_size) {
    const float* x  = (const float*)d_in[0];
    const int*   ei = (const int*)d_in[1];
    const float *w1a = (const float*)d_in[2],  *b1a = (const float*)d_in[3];
    const float *ga  = (const float*)d_in[4],  *bea = (const float*)d_in[5];
    const float *ma  = (const float*)d_in[6],  *va  = (const float*)d_in[7];
    const float *w2a = (const float*)d_in[8],  *b2a = (const float*)d_in[9];
    const float *w1b = (const float*)d_in[10], *b1b = (const float*)d_in[11];
    const float *gb  = (const float*)d_in[12], *beb = (const float*)d_in[13];
    const float *mb  = (const float*)d_in[14], *vb  = (const float*)d_in[15];
    const float *w2b = (const float*)d_in[16], *b2b = (const float*)d_in[17];
    const float *fcw = (const float*)d_in[18], *fcb = (const float*)d_in[19];
    const float *l1w = (const float*)d_in[20], *l1b = (const float*)d_in[21];
    const float *l2w = (const float*)d_in[22], *l2b = (const float*)d_in[23];
    const float *ow  = (const float*)d_in[24], *ob  = (const float*)d_in[25];
    float* out = (float*)d_out;

    // one-time host-handle setup (no device memory)
    static cudaStream_t s2 = nullptr;
    static cudaEvent_t e1 = nullptr, e2 = nullptr, eW1 = nullptr, eW2 = nullptr,
                       eFC = nullptr;
    static bool attr = false;
    if (!attr) {
        cudaFuncSetAttribute(gemm_mma_kernel<256, 128, 512>,
                             cudaFuncAttributeMaxDynamicSharedMemorySize,
                             STAGES * (256 * 64 + 128 * 64));
        cudaFuncSetAttribute(gemm_mma_kernel<128, 64, 256>,
                             cudaFuncAttributeMaxDynamicSharedMemorySize,
                             STAGES * (128 * 64 + 64 * 64));
        cudaStreamCreateWithFlags(&s2, cudaStreamNonBlocking);
        cudaEventCreateWithFlags(&e1,  cudaEventDisableTiming);
        cudaEventCreateWithFlags(&e2,  cudaEventDisableTiming);
        cudaEventCreateWithFlags(&eW1, cudaEventDisableTiming);
        cudaEventCreateWithFlags(&eW2, cudaEventDisableTiming);
        cudaEventCreateWithFlags(&eFC, cudaEventDisableTiming);
        attr = true;
    }

    float* h = sym(g_h);
    f16 *hf  = sym(g_hf);
    f16 *t   = sym(g_t);
    f16 *c   = sym(g_c);
    f16 *fcv = sym(g_fc);
    f16 *w1s = sym(g_w1ab);
    f16 *w2as = sym(g_w2a), *w2bs = sym(g_w2b);
    f16 *wfs = sym(g_wfc);
    f16 *wl1s = sym(g_wl1), *wl2s = sym(g_wl2);
    f16 *wos = sym(g_wo);
    f16 *w2c = sym(g_w2c);
    f16 *wall = sym(g_wall);
    float *bias1 = sym(g_bias1), *ball = sym(g_ball), *zerob = sym(g_zerobias);
    float *bnb = sym(g_bnb), *bng = sym(g_bng), *bnbt = sym(g_bnbt);
    float *bnm = sym(g_bnm), *bnv = sym(g_bnv);

    const int n_edges = in_sizes[1] / 2;
    cudaStream_t ms = 0;

    cudaEventRecord(e1, ms);

    // ---- side chain (s2): ALL weight prep ----
    cudaStreamWaitEvent(s2, e1, 0);
    {
        dim3 b(32, 8);
        // 1) w1 trans + BN concat (needed by mm1)
        wtrans2_kernel<<<dim3(HID / 32, IN_C / 32, 2), b, 0, s2>>>(
            w1a, w1b, w1s, w1s + HID * IN_C, IN_C, HID);
        concat_bn_kernel<<<2, 256, 0, s2>>>(b1a, b1b, ga, gb, bea, beb, ma, mb, va, vb);
        cudaEventRecord(eW1, s2);
        // 2) w2 trans (needed by mm2)
        wtrans2_kernel<<<dim3(HID / 32, HID / 32, 2), b, 0, s2>>>(
            w2a, w2b, w2as, w2bs, HID, HID);
        cudaEventRecord(eW2, s2);
        // 3) fc weight
        wtrans_kernel<<<dim3(D_FC / 32, D_CAT / 32), b, 0, s2>>>(fcw, wfs, D_CAT, D_FC);
        cudaEventRecord(eFC, s2);
        // 4) tail fold chain
        wtrans_kernel<<<dim3(OUT_C / 32, D_FC / 32), b, 0, s2>>>(ow, wos, D_FC, OUT_C);
        int n14 = D_FC * D_L1 / 4;
        conv2_kernel<<<(2 * n14 + 255) / 256, 256, 0, s2>>>(
            (const float4*)l1w, (const float4*)l2w, (uint2*)wl1s, (uint2*)wl2s, n14);
        bias_fold_kernel<<<D_FC / 256, 256, 0, s2>>>(l1b, l2w, l2b, bias1);
        bias_fold2_kernel<<<1, OUT_C, 0, s2>>>(bias1, ow, ob, ball);
        launch_gemm<128, 64, 256>(s2, wos, wl2s, w2c, 0, zerob, 0, 0, 0, 0,
                                  OUT_C, D_L1, D_FC, D_FC, D_L1, EPI_NONE);
        launch_gemm<128, 64, 256>(s2, w2c, wl1s, wall, 0, zerob, 0, 0, 0, 0,
                                  OUT_C, D_FC, D_L1, D_L1, D_FC, EPI_NONE);
        cudaEventRecord(e2, s2);
    }

    // ---- main chain: x-dependent path ----
    {
        int n4 = NN * IN_C / 4;
        copy_x_kernel<<<(n4 + 255) / 256, 256, 0, ms>>>((const float4*)x, (float4*)h, n4);
        long long nthreads = (long long)n_edges * 32;
        edge_agg_kernel<<<(int)((nthreads + 255) / 256), 256, 0, ms>>>(x, ei, h, n_edges);
        conv_kernel<<<(n4 + 255) / 256, 256, 0, ms>>>((const float4*)h, (uint2*)hf, n4);
    }
    // mm1
    cudaStreamWaitEvent(ms, eW1, 0);
    launch_gemm<256, 128, 512>(ms, hf, w1s, t, 0, bnb, bng, bnbt, bnm, bnv,
                               NN, D_CAT, IN_C, IN_C, D_CAT, EPI_BNRELU);

    // merged mm2 (grid.z = 2: z=0 -> w2a half, z=1 -> w2b half)
    cudaStreamWaitEvent(ms, eW2, 0);
    launch_gemm_dual<256, 128, 512>(ms, t, w2as, w2bs, c, b2a, b2b,
                                    HID, HID, NN, HID, HID, D_CAT, D_CAT, EPI_RELU);

    // fc (single launch)
    cudaStreamWaitEvent(ms, eFC, 0);
    launch_gemm<256, 128, 512>(ms, c, wfs, fcv, 0, fcb, 0, 0, 0, 0,
                               NN, D_FC, D_CAT, D_CAT, D_FC, EPI_LEAKY);

    // folded tail (single launch)
    cudaStreamWaitEvent(ms, e2, 0);
    launch_gemm<128, 64, 256>(ms, fcv, wall, 0, out, ball, 0, 0, 0, 0,
                              NN, OUT_C, D_FC, D_FC, OUT_C, EPI_SIGMOID);
}

// round 17
// speedup vs baseline: 1.0879x; 1.0879x over previous
#include <cuda_runtime.h>
#include <cuda_fp16.h>
#include <math.h>
#include <stdint.h>

#define NN      60000
#define IN_C    128
#define HID     512
#define D_CAT   1024
#define D_FC    2048
#define D_L1    4096
#define OUT_C   64
#define BN_EPS  1e-5f
#define M_SPLIT 29952          // 117 * 256

#define EPI_NONE    0
#define EPI_RELU    1
#define EPI_BNRELU  2
#define EPI_LEAKY   3
#define EPI_SIGMOID 4

typedef __half f16;

// ---------------------------------------------------------------------------
// Scratch (__device__ globals; no allocations allowed)
// ---------------------------------------------------------------------------
__device__ float g_h[(size_t)NN * IN_C];
__device__ f16  g_hf [(size_t)NN * IN_C ];
__device__ f16  g_t  [(size_t)NN * D_CAT];
__device__ f16  g_c  [(size_t)NN * D_CAT];
__device__ f16  g_fc [(size_t)NN * D_FC ];
// weights fp16 [N,K]
__device__ f16 g_w1ab[D_CAT * IN_C];
__device__ f16 g_w2a[HID * HID];
__device__ f16 g_w2b[HID * HID];
__device__ f16 g_wfc[D_FC * D_CAT];
__device__ f16 g_wl1[(size_t)D_FC * D_L1];
__device__ f16 g_wl2[(size_t)D_L1 * D_FC];
__device__ f16 g_wo [OUT_C * D_FC];
// fold intermediates / results
__device__ f16  g_w2c [OUT_C * D_L1];
__device__ f16  g_wall[OUT_C * D_FC];
__device__ float g_bias1[D_FC];
__device__ float g_ball [OUT_C];
__device__ float g_zerobias[D_L1];
// concatenated BN params
__device__ float g_bnb[D_CAT], g_bng[D_CAT], g_bnbt[D_CAT], g_bnm[D_CAT], g_bnv[D_CAT];

// ---------------------------------------------------------------------------
// helpers
// ---------------------------------------------------------------------------
__device__ __forceinline__ uint32_t smem_u32(const void* p) {
    uint32_t a;
    asm("{ .reg .u64 t; cvta.to.shared.u64 t, %1; cvt.u32.u64 %0, t; }" : "=r"(a) : "l"(p));
    return a;
}

#define LDSM4(r, a) \
    asm volatile("ldmatrix.sync.aligned.m8n8.x4.shared.b16 {%0,%1,%2,%3}, [%4];" \
        : "=r"((r)[0]), "=r"((r)[1]), "=r"((r)[2]), "=r"((r)[3]) : "r"(a))

#define MMA_F16(d, a, b) \
    asm volatile("mma.sync.aligned.m16n8k16.row.col.f32.f16.f16.f32 " \
        "{%0,%1,%2,%3}, {%4,%5,%6,%7}, {%8,%9}, {%0,%1,%2,%3};" \
        : "+f"((d)[0]), "+f"((d)[1]), "+f"((d)[2]), "+f"((d)[3]) \
        : "r"((a)[0]), "r"((a)[1]), "r"((a)[2]), "r"((a)[3]), "r"((b)[0]), "r"((b)[1]))

#define CP_ASYNC(dst, src, ok) \
    asm volatile("cp.async.cg.shared.global [%0], [%1], 16, %2;" \
        :: "r"(dst), "l"(src), "r"(ok) : "memory")
#define CP_COMMIT()  asm volatile("cp.async.commit_group;" ::: "memory")
#define CP_WAIT2()   asm volatile("cp.async.wait_group 2;" ::: "memory")

// ---------------------------------------------------------------------------
// small kernels
// ---------------------------------------------------------------------------
__global__ void copy_x_kernel(const float4* __restrict__ x, float4* __restrict__ h, int n4) {
    int i = blockIdx.x * blockDim.x + threadIdx.x;
    if (i < n4) h[i] = x[i];
}

__global__ void edge_agg_kernel(const float* __restrict__ x, const int* __restrict__ ei,
                                float* __restrict__ h, int n_edges) {
    int warp = (blockIdx.x * blockDim.x + threadIdx.x) >> 5;
    int lane = threadIdx.x & 31;
    if (warp >= n_edges) return;
    int src = ei[warp];
    int dst = ei[n_edges + warp];
    const float4 v = *reinterpret_cast<const float4*>(x + (size_t)src * IN_C + lane * 4);
    float* d = h + (size_t)dst * IN_C + lane * 4;
    asm volatile("red.global.add.v4.f32 [%0], {%1, %2, %3, %4};"
                 :: "l"(d), "f"(v.x), "f"(v.y), "f"(v.z), "f"(v.w) : "memory");
}

// fp32 -> fp16 convert, 4 / thread
__global__ void conv_kernel(const float4* __restrict__ in, uint2* __restrict__ o, int n4) {
    int i = blockIdx.x * blockDim.x + threadIdx.x;
    if (i >= n4) return;
    float4 v = in[i];
    __half2 h01 = __floats2half2_rn(v.x, v.y);
    __half2 h23 = __floats2half2_rn(v.z, v.w);
    uint2 u; u.x = *(uint32_t*)&h01; u.y = *(uint32_t*)&h23;
    o[i] = u;
}

// two fp32 -> fp16 converts in one launch
__global__ void conv2_kernel(const float4* __restrict__ a, const float4* __restrict__ b,
                             uint2* __restrict__ ao, uint2* __restrict__ bo, int n4) {
    int i = blockIdx.x * blockDim.x + threadIdx.x;
    const float4* src; uint2* dst; int idx;
    if (i < n4)          { src = a; dst = ao; idx = i; }
    else if (i < 2 * n4) { src = b; dst = bo; idx = i - n4; }
    else return;
    float4 v = src[idx];
    __half2 h01 = __floats2half2_rn(v.x, v.y);
    __half2 h23 = __floats2half2_rn(v.z, v.w);
    uint2 u; u.x = *(uint32_t*)&h01; u.y = *(uint32_t*)&h23;
    dst[idx] = u;
}

// paired transpose -> fp16: z selects (W, dst)
__global__ void wtrans2_kernel(const float* __restrict__ W0, const float* __restrict__ W1,
                               f16* o0, f16* o1, int K, int N) {
    const float* W = blockIdx.z ? W1 : W0;
    f16* o = blockIdx.z ? o1 : o0;
    __shared__ float t[32][33];
    int n0 = blockIdx.x * 32, k0 = blockIdx.y * 32;
#pragma unroll
    for (int dy = 0; dy < 32; dy += 8) {
        int k = k0 + threadIdx.y + dy, n = n0 + threadIdx.x;
        t[threadIdx.y + dy][threadIdx.x] = (k < K && n < N) ? W[(size_t)k * N + n] : 0.f;
    }
    __syncthreads();
#pragma unroll
    for (int dy = 0; dy < 32; dy += 8) {
        int n = n0 + threadIdx.y + dy, k = k0 + threadIdx.x;
        if (n < N && k < K)
            o[(size_t)n * K + k] = __float2half(t[threadIdx.x][threadIdx.y + dy]);
    }
}

__global__ void wtrans_kernel(const float* __restrict__ W, f16* __restrict__ o, int K, int N) {
    __shared__ float t[32][33];
    int n0 = blockIdx.x * 32, k0 = blockIdx.y * 32;
#pragma unroll
    for (int dy = 0; dy < 32; dy += 8) {
        int k = k0 + threadIdx.y + dy, n = n0 + threadIdx.x;
        t[threadIdx.y + dy][threadIdx.x] = (k < K && n < N) ? W[(size_t)k * N + n] : 0.f;
    }
    __syncthreads();
#pragma unroll
    for (int dy = 0; dy < 32; dy += 8) {
        int n = n0 + threadIdx.y + dy, k = k0 + threadIdx.x;
        if (n < N && k < K)
            o[(size_t)n * K + k] = __float2half(t[threadIdx.x][threadIdx.y + dy]);
    }
}

__global__ void concat_bn_kernel(const float* b1a, const float* b1b,
                                 const float* ga,  const float* gb,
                                 const float* bea, const float* beb,
                                 const float* ma,  const float* mb,
                                 const float* va,  const float* vb) {
    int i = threadIdx.x + blockIdx.x * blockDim.x;
    if (i >= HID) return;
    g_bnb [i] = b1a[i];  g_bnb [HID + i] = b1b[i];
    g_bng [i] = ga[i];   g_bng [HID + i] = gb[i];
    g_bnbt[i] = bea[i];  g_bnbt[HID + i] = beb[i];
    g_bnm [i] = ma[i];   g_bnm [HID + i] = mb[i];
    g_bnv [i] = va[i];   g_bnv [HID + i] = vb[i];
}

__global__ void bias_fold_kernel(const float* __restrict__ l1b,
                                 const float* __restrict__ l2w,
                                 const float* __restrict__ l2b,
                                 float* __restrict__ outb) {
    int n = blockIdx.x * blockDim.x + threadIdx.x;
    if (n >= D_FC) return;
    float s = l2b[n];
    for (int k = 0; k < D_L1; k++)
        s += l1b[k] * l2w[(size_t)k * D_FC + n];
    outb[n] = s;
}

__global__ void bias_fold2_kernel(const float* __restrict__ b1,
                                  const float* __restrict__ ow,
                                  const float* __restrict__ outb,
                                  float* __restrict__ ball) {
    int j = threadIdx.x;
    if (j >= OUT_C) return;
    float s = outb[j];
    for (int n = 0; n < D_FC; n++)
        s += b1[n] * ow[(size_t)n * OUT_C + j];
    ball[j] = s;
}

// ---------------------------------------------------------------------------
// fp16 mma.sync GEMM: C[M,N] = A[M,K](lda) @ B[N,K]^T, fp32 accumulate
// ---------------------------------------------------------------------------
#define STAGES 4

template <int BM_T, int BN_T, int TH>
__global__ __launch_bounds__(TH, 1)
void gemm_mma_kernel(const f16* __restrict__ A_g, const f16* __restrict__ B_g,
                     f16* __restrict__ C16, float* __restrict__ Cf,
                     const float* __restrict__ bias,
                     const float* __restrict__ gamma, const float* __restrict__ beta,
                     const float* __restrict__ mean,  const float* __restrict__ var,
                     int M, int N, int K, int lda, int ldc, int epi)
{
    constexpr int A_BY   = BM_T * 64;
    constexpr int B_BY   = BN_T * 64;
    constexpr int OFF_B  = A_BY;
    constexpr int STG_B  = A_BY + B_BY;
    constexpr int WM     = TH / 64;
    constexpr int WTM    = BM_T / WM;
    constexpr int NI     = WTM / 16;
    constexpr int NJ     = BN_T / 16;
    constexpr int NJJ    = BN_T / 32;
    constexpr int A_IDS  = BM_T * 4;
    constexpr int PER    = (BM_T * 4 + BN_T * 4) / TH;

    extern __shared__ __align__(128) char smem[];
    const uint32_t sb = smem_u32(smem);
    const int tid = threadIdx.x;
    const int lid = tid & 31, wid = tid >> 5;
    const int warpM = wid >> 1, warpN = wid & 1;
    const int m0 = blockIdx.y * BM_T, n0 = blockIdx.x * BN_T;
    const int NC = K >> 5;

    float acc[NI][NJ][4];
#pragma unroll
    for (int i = 0; i < NI; i++)
#pragma unroll
        for (int j = 0; j < NJ; j++)
#pragma unroll
            for (int q = 0; q < 4; q++) acc[i][j][q] = 0.0f;

    auto issue_stage = [&](int c, int s) {
        const int k0 = c << 5;
        const uint32_t stb = sb + s * STG_B;
#pragma unroll
        for (int q = 0; q < PER; q++) {
            int id = q * TH + tid;
            const f16* base;
            uint32_t toff;
            int row, ch, gr, rmax, ld;
            if (id < A_IDS) {
                row = id >> 2; ch = id & 3;
                base = A_g; toff = 0u;
                gr = m0 + row; rmax = M; ld = lda;
            } else {
                int idx = id - A_IDS;
                row = idx >> 2; ch = idx & 3;
                base = B_g; toff = (uint32_t)OFF_B;
                gr = n0 + row; rmax = N; ld = K;
            }
            unsigned ok = (gr < rmax) ? 16u : 0u;
            int rc = (gr < rmax) ? gr : 0;
            const char* src = (const char*)(base + (size_t)rc * ld + k0) + ch * 16;
            uint32_t dst = stb + toff + row * 64 + ((ch ^ ((row >> 1) & 3)) << 4);
            CP_ASYNC(dst, src, ok);
        }
        CP_COMMIT();
    };

    issue_stage(0, 0);
    issue_stage(1, 1);
    issue_stage(2, 2);

    const int grp = lid >> 3, lr = lid & 7;

    int s = 0;
    for (int c = 0; c < NC; c++) {
        CP_WAIT2();
        __syncthreads();
        if (c + 3 < NC) issue_stage(c + 3, (s + 3) & 3);
        else CP_COMMIT();

        const uint32_t stb = sb + s * STG_B;
#pragma unroll
        for (int ks = 0; ks < 2; ks++) {
            uint32_t a[NI][4];
#pragma unroll
            for (int i = 0; i < NI; i++) {
                int row = warpM * WTM + i * 16 + lr + ((grp & 1) << 3);
                int chk = 2 * ks + (grp >> 1);
                uint32_t ad = stb + row * 64 + ((chk ^ ((row >> 1) & 3)) << 4);
                LDSM4(a[i], ad);
            }
            uint32_t b[NJ][2];
#pragma unroll
            for (int jj = 0; jj < NJJ; jj++) {
                int row = warpN * (BN_T / 2) + jj * 16 + lr + ((grp >= 2) ? 8 : 0);
                int chk = 2 * ks + (grp & 1);
                uint32_t bd = stb + OFF_B + row * 64 + ((chk ^ ((row >> 1) & 3)) << 4);
                uint32_t r[4];
                LDSM4(r, bd);
                b[2 * jj][0] = r[0]; b[2 * jj][1] = r[1];
                b[2 * jj + 1][0] = r[2]; b[2 * jj + 1][1] = r[3];
            }
#pragma unroll
            for (int i = 0; i < NI; i++)
#pragma unroll
                for (int j = 0; j < NJ; j++)
                    MMA_F16(acc[i][j], a[i], b[j]);
        }
        s = (s + 1) & 3;
    }

    // ---- epilogue ----
    const int r_base = m0 + warpM * WTM + (lid >> 2);
    const int c_base = n0 + warpN * (BN_T / 2) + (lid & 3) * 2;
#pragma unroll
    for (int i = 0; i < NI; i++) {
#pragma unroll
        for (int half_r = 0; half_r < 2; half_r++) {
            int row = r_base + i * 16 + half_r * 8;
            if (row >= M) continue;
#pragma unroll
            for (int j = 0; j < NJ; j++) {
                int col = c_base + j * 8;
                if (col >= N) continue;
                float v0 = acc[i][j][half_r * 2 + 0] + bias[col];
                float v1 = acc[i][j][half_r * 2 + 1] + bias[col + 1];
                if (epi == EPI_BNRELU) {
                    v0 = (v0 - mean[col])     * rsqrtf(var[col] + BN_EPS)     * gamma[col]     + beta[col];
                    v1 = (v1 - mean[col + 1]) * rsqrtf(var[col + 1] + BN_EPS) * gamma[col + 1] + beta[col + 1];
                    v0 = fmaxf(v0, 0.0f); v1 = fmaxf(v1, 0.0f);
                } else if (epi == EPI_RELU) {
                    v0 = fmaxf(v0, 0.0f); v1 = fmaxf(v1, 0.0f);
                } else if (epi == EPI_LEAKY) {
                    v0 = (v0 > 0.0f) ? v0 : 0.01f * v0;
                    v1 = (v1 > 0.0f) ? v1 : 0.01f * v1;
                }
                if (epi == EPI_SIGMOID) {
                    float2 o;
                    o.x = 1.0f / (1.0f + expf(-v0));
                    o.y = 1.0f / (1.0f + expf(-v1));
                    *(float2*)(Cf + (size_t)row * ldc + col) = o;
                } else {
                    *(__half2*)(C16 + (size_t)row * ldc + col) = __floats2half2_rn(v0, v1);
                }
            }
        }
    }
}

// ---------------------------------------------------------------------------
// launch helpers
// ---------------------------------------------------------------------------
template <int BM_T, int BN_T, int TH>
static void launch_gemm(cudaStream_t st,
                        const f16* A, const f16* B,
                        f16* C16, float* Cf, const float* bias,
                        const float* ga, const float* be, const float* me, const float* va,
                        int M, int N, int K, int lda, int ldc, int epi) {
    dim3 grid((N + BN_T - 1) / BN_T, (M + BM_T - 1) / BM_T, 1);
    int smem = STAGES * (BM_T * 64 + BN_T * 64);
    gemm_mma_kernel<BM_T, BN_T, TH><<<grid, TH, smem, st>>>(
        A, B, C16, Cf, bias, ga, be, me, va, M, N, K, lda, ldc, epi);
}

template <typename T> static T* sym(T* symbol) {
    void* p = nullptr;
    cudaGetSymbolAddress(&p, (const void*)symbol);
    return (T*)p;
}

extern "C" void kernel_launch(void* const* d_in, const int* in_sizes, int n_in,
                              void* d_out, int out_size) {
    const float* x  = (const float*)d_in[0];
    const int*   ei = (const int*)d_in[1];
    const float *w1a = (const float*)d_in[2],  *b1a = (const float*)d_in[3];
    const float *ga  = (const float*)d_in[4],  *bea = (const float*)d_in[5];
    const float *ma  = (const float*)d_in[6],  *va  = (const float*)d_in[7];
    const float *w2a = (const float*)d_in[8],  *b2a = (const float*)d_in[9];
    const float *w1b = (const float*)d_in[10], *b1b = (const float*)d_in[11];
    const float *gb  = (const float*)d_in[12], *beb = (const float*)d_in[13];
    const float *mb  = (const float*)d_in[14], *vb  = (const float*)d_in[15];
    const float *w2b = (const float*)d_in[16], *b2b = (const float*)d_in[17];
    const float *fcw = (const float*)d_in[18], *fcb = (const float*)d_in[19];
    const float *l1w = (const float*)d_in[20], *l1b = (const float*)d_in[21];
    const float *l2w = (const float*)d_in[22], *l2b = (const float*)d_in[23];
    const float *ow  = (const float*)d_in[24], *ob  = (const float*)d_in[25];
    float* out = (float*)d_out;

    // one-time host-handle setup (no device memory)
    static cudaStream_t s2 = nullptr, s3 = nullptr;
    static cudaEvent_t e1 = nullptr, e2 = nullptr, eW2 = nullptr, eFC = nullptr,
                       eM1 = nullptr, eB = nullptr, eF0 = nullptr, eT0 = nullptr;
    static bool attr = false;
    if (!attr) {
        cudaFuncSetAttribute(gemm_mma_kernel<256, 128, 512>,
                             cudaFuncAttributeMaxDynamicSharedMemorySize,
                             STAGES * (256 * 64 + 128 * 64));
        cudaFuncSetAttribute(gemm_mma_kernel<128, 64, 256>,
                             cudaFuncAttributeMaxDynamicSharedMemorySize,
                             STAGES * (128 * 64 + 64 * 64));
        cudaStreamCreateWithFlags(&s2, cudaStreamNonBlocking);
        cudaStreamCreateWithFlags(&s3, cudaStreamNonBlocking);
        cudaEventCreateWithFlags(&e1,  cudaEventDisableTiming);
        cudaEventCreateWithFlags(&e2,  cudaEventDisableTiming);
        cudaEventCreateWithFlags(&eW2, cudaEventDisableTiming);
        cudaEventCreateWithFlags(&eFC, cudaEventDisableTiming);
        cudaEventCreateWithFlags(&eM1, cudaEventDisableTiming);
        cudaEventCreateWithFlags(&eB,  cudaEventDisableTiming);
        cudaEventCreateWithFlags(&eF0, cudaEventDisableTiming);
        cudaEventCreateWithFlags(&eT0, cudaEventDisableTiming);
        attr = true;
    }

    float* h = sym(g_h);
    f16 *hf  = sym(g_hf);
    f16 *t   = sym(g_t);
    f16 *c   = sym(g_c);
    f16 *fcv = sym(g_fc);
    f16 *w1s = sym(g_w1ab);
    f16 *w2as = sym(g_w2a), *w2bs = sym(g_w2b);
    f16 *wfs = sym(g_wfc);
    f16 *wl1s = sym(g_wl1), *wl2s = sym(g_wl2);
    f16 *wos = sym(g_wo);
    f16 *w2c = sym(g_w2c);
    f16 *wall = sym(g_wall);
    float *bias1 = sym(g_bias1), *ball = sym(g_ball), *zerob = sym(g_zerobias);
    float *bnb = sym(g_bnb), *bng = sym(g_bng), *bnbt = sym(g_bnbt);
    float *bnm = sym(g_bnm), *bnv = sym(g_bnv);

    const int n_edges = in_sizes[1] / 2;
    cudaStream_t ms = 0;

    cudaEventRecord(e1, ms);

    // ---- side chain (s2): weight prep (R14 arrangement) ----
    cudaStreamWaitEvent(s2, e1, 0);
    {
        dim3 b(32, 8);
        wtrans2_kernel<<<dim3(HID / 32, HID / 32, 2), b, 0, s2>>>(
            w2a, w2b, w2as, w2bs, HID, HID);
        cudaEventRecord(eW2, s2);
        wtrans_kernel<<<dim3(D_FC / 32, D_CAT / 32), b, 0, s2>>>(fcw, wfs, D_CAT, D_FC);
        cudaEventRecord(eFC, s2);
        wtrans_kernel<<<dim3(OUT_C / 32, D_FC / 32), b, 0, s2>>>(ow, wos, D_FC, OUT_C);
        int n14 = D_FC * D_L1 / 4;
        conv2_kernel<<<(2 * n14 + 255) / 256, 256, 0, s2>>>(
            (const float4*)l1w, (const float4*)l2w, (uint2*)wl1s, (uint2*)wl2s, n14);
        bias_fold_kernel<<<D_FC / 256, 256, 0, s2>>>(l1b, l2w, l2b, bias1);
        bias_fold2_kernel<<<1, OUT_C, 0, s2>>>(bias1, ow, ob, ball);
        launch_gemm<128, 64, 256>(s2, wos, wl2s, w2c, 0, zerob, 0, 0, 0, 0,
                                  OUT_C, D_L1, D_FC, D_FC, D_L1, EPI_NONE);
        launch_gemm<128, 64, 256>(s2, w2c, wl1s, wall, 0, zerob, 0, 0, 0, 0,
                                  OUT_C, D_FC, D_L1, D_L1, D_FC, EPI_NONE);
        cudaEventRecord(e2, s2);
    }

    // ---- main chain: x-dependent path (R14 arrangement) ----
    {
        int n4 = NN * IN_C / 4;
        copy_x_kernel<<<(n4 + 255) / 256, 256, 0, ms>>>((const float4*)x, (float4*)h, n4);
        long long nthreads = (long long)n_edges * 32;
        edge_agg_kernel<<<(int)((nthreads + 255) / 256), 256, 0, ms>>>(x, ei, h, n_edges);
        conv_kernel<<<(n4 + 255) / 256, 256, 0, ms>>>((const float4*)h, (uint2*)hf, n4);
        dim3 b(32, 8);
        wtrans2_kernel<<<dim3(HID / 32, IN_C / 32, 2), b, 0, ms>>>(
            w1a, w1b, w1s, w1s + HID * IN_C, IN_C, HID);
        concat_bn_kernel<<<2, 256, 0, ms>>>(b1a, b1b, ga, gb, bea, beb, ma, mb, va, vb);
    }
    // mm1
    launch_gemm<256, 128, 512>(ms, hf, w1s, t, 0, bnb, bng, bnbt, bnm, bnv,
                               NN, D_CAT, IN_C, IN_C, D_CAT, EPI_BNRELU);
    cudaEventRecord(eM1, ms);

    // mm2b on s3 (parallel with mm2a on ms) — R14 two-stream arrangement
    cudaStreamWaitEvent(s3, eM1, 0);
    cudaStreamWaitEvent(s3, eW2, 0);
    launch_gemm<256, 128, 512>(s3, t + HID, w2bs, c + HID, 0, b2b,
                               0, 0, 0, 0, NN, HID, HID, D_CAT, D_CAT, EPI_RELU);
    cudaEventRecord(eB, s3);

    // mm2a on ms
    cudaStreamWaitEvent(ms, eW2, 0);
    launch_gemm<256, 128, 512>(ms, t, w2as, c, 0, b2a, 0, 0, 0, 0,
                               NN, HID, HID, D_CAT, D_CAT, EPI_RELU);

    // fc, M-split into two halves (measured good: R15 vs R16)
    cudaStreamWaitEvent(ms, eB, 0);
    cudaStreamWaitEvent(ms, eFC, 0);
    launch_gemm<256, 128, 512>(ms, c, wfs, fcv, 0, fcb, 0, 0, 0, 0,
                               M_SPLIT, D_FC, D_CAT, D_CAT, D_FC, EPI_LEAKY);
    cudaEventRecord(eF0, ms);
    launch_gemm<256, 128, 512>(ms, c + (size_t)M_SPLIT * D_CAT, wfs,
                               fcv + (size_t)M_SPLIT * D_FC, 0, fcb, 0, 0, 0, 0,
                               NN - M_SPLIT, D_FC, D_CAT, D_CAT, D_FC, EPI_LEAKY);

    // tail half 0 on s3 (overlaps fc half 1)
    cudaStreamWaitEvent(s3, eF0, 0);
    cudaStreamWaitEvent(s3, e2, 0);
    launch_gemm<128, 64, 256>(s3, fcv, wall, 0, out, ball, 0, 0, 0, 0,
                              M_SPLIT, OUT_C, D_FC, D_FC, OUT_C, EPI_SIGMOID);
    cudaEventRecord(eT0, s3);

    // tail half 1 on ms
    cudaStreamWaitEvent(ms, e2, 0);
    launch_gemm<128, 64, 256>(ms, fcv + (size_t)M_SPLIT * D_FC, wall, 0,
                              out + (size_t)M_SPLIT * OUT_C, ball, 0, 0, 0, 0,
                              NN - M_SPLIT, OUT_C, D_FC, D_FC, OUT_C, EPI_SIGMOID);

    // join s3 back into ms before capture end
    cudaStreamWaitEvent(ms, eT0, 0);
}